// round 12
// baseline (speedup 1.0000x reference)
#include <cuda_runtime.h>
#include <cuda_bf16.h>
#include <cstdint>
#include <math.h>

#define T_TOK 2048
#define D_DIM 1024
#define F_DIM 2048
#define NE 8

// ---- scratch: referenced ONLY inside device code ----
__device__ __nv_bfloat16 g_sWgh[(size_t)D_DIM * F_DIM], g_sWgl[(size_t)D_DIM * F_DIM];
__device__ __nv_bfloat16 g_sWuh[(size_t)D_DIM * F_DIM], g_sWul[(size_t)D_DIM * F_DIM];
__device__ __nv_bfloat16 g_sWdh[(size_t)F_DIM * D_DIM], g_sWdl[(size_t)F_DIM * D_DIM];
__device__ __nv_bfloat16 g_Xh [(size_t)T_TOK * D_DIM], g_Xl [(size_t)T_TOK * D_DIM];
__device__ __nv_bfloat16 g_Xeh[(size_t)T_TOK * D_DIM], g_Xel[(size_t)T_TOK * D_DIM];
__device__ __nv_bfloat16 g_Hh [(size_t)T_TOK * F_DIM], g_Hl [(size_t)T_TOK * F_DIM];
__device__ __nv_bfloat16 g_H2h[(size_t)T_TOK * F_DIM], g_H2l[(size_t)T_TOK * F_DIM];
__device__ float g_O2[(size_t)T_TOK * D_DIM];
__device__ int   g_tok_e[T_TOK];
__device__ float g_tok_s[T_TOK];
__device__ int   g_row[T_TOK];
__device__ int   g_order[T_TOK];
__device__ int   g_offs[NE + 1];

__device__ __forceinline__ float silu_f(float x) { return x / (1.0f + expf(-x)); }

__device__ __forceinline__ void split2(float x0, float x1, unsigned &hi, unsigned &lo) {
    __nv_bfloat16 h0 = __float2bfloat16_rn(x0), h1 = __float2bfloat16_rn(x1);
    hi = (unsigned)__bfloat16_as_ushort(h0) | ((unsigned)__bfloat16_as_ushort(h1) << 16);
    float r0 = x0 - __bfloat162float(h0), r1 = x1 - __bfloat162float(h1);
    lo = (unsigned)__bfloat16_as_ushort(__float2bfloat16_rn(r0))
       | ((unsigned)__bfloat16_as_ushort(__float2bfloat16_rn(r1)) << 16);
}

__device__ __forceinline__ void cpa16(void* smem, const void* gmem) {
    unsigned s = (unsigned)__cvta_generic_to_shared(smem);
    asm volatile("cp.async.cg.shared.global [%0], [%1], 16;" :: "r"(s), "l"(gmem));
}
__device__ __forceinline__ void cpa_commit() { asm volatile("cp.async.commit_group;"); }
template <int N> __device__ __forceinline__ void cpa_wait() {
    asm volatile("cp.async.wait_group %0;" :: "n"(N) : "memory");
}

__device__ __forceinline__ void ldsm4(unsigned r[4], const void* p) {
    unsigned a = (unsigned)__cvta_generic_to_shared(p);
    asm volatile("ldmatrix.sync.aligned.m8n8.x4.shared.b16 {%0,%1,%2,%3}, [%4];"
                 : "=r"(r[0]), "=r"(r[1]), "=r"(r[2]), "=r"(r[3]) : "r"(a));
}
__device__ __forceinline__ void ldsm4t(unsigned r[4], const void* p) {
    unsigned a = (unsigned)__cvta_generic_to_shared(p);
    asm volatile("ldmatrix.sync.aligned.m8n8.x4.trans.shared.b16 {%0,%1,%2,%3}, [%4];"
                 : "=r"(r[0]), "=r"(r[1]), "=r"(r[2]), "=r"(r[3]) : "r"(a));
}
__device__ __forceinline__ void mma_bf16(float c[4], const unsigned a[4], unsigned b0, unsigned b1) {
    asm volatile(
        "mma.sync.aligned.m16n8k16.row.col.f32.bf16.bf16.f32 "
        "{%0,%1,%2,%3}, {%4,%5,%6,%7}, {%8,%9}, {%0,%1,%2,%3};"
        : "+f"(c[0]), "+f"(c[1]), "+f"(c[2]), "+f"(c[3])
        : "r"(a[0]), "r"(a[1]), "r"(a[2]), "r"(a[3]), "r"(b0), "r"(b1));
}

// ---------------- convert shared weights only (high reuse) ----------------
__global__ void conv_shared(const float* __restrict__ g, const float* __restrict__ u,
                            const float* __restrict__ d) {
    const int n4 = D_DIM * F_DIM / 4;
    for (int idx = blockIdx.x * 256 + threadIdx.x; idx < 3 * n4; idx += gridDim.x * 256) {
        int which = idx / n4, i = idx - which * n4;
        const float* src = (which == 0) ? g : (which == 1) ? u : d;
        __nv_bfloat16* dh = (which == 0) ? g_sWgh : (which == 1) ? g_sWuh : g_sWdh;
        __nv_bfloat16* dl = (which == 0) ? g_sWgl : (which == 1) ? g_sWul : g_sWdl;
        float4 v = ((const float4*)src)[i];
        unsigned h0, l0, h1, l1;
        split2(v.x, v.y, h0, l0); split2(v.z, v.w, h1, l1);
        ((unsigned*)dh)[2 * i] = h0; ((unsigned*)dh)[2 * i + 1] = h1;
        ((unsigned*)dl)[2 * i] = l0; ((unsigned*)dl)[2 * i + 1] = l1;
    }
}

// ---------------- router ----------------
__global__ void router_kernel(const float* __restrict__ x, const float* __restrict__ rw) {
    __shared__ float red[256][NE + 1];
    int t = blockIdx.x, tid = threadIdx.x;
    float4 xa = ((const float4*)(x + (size_t)t * D_DIM))[tid];
#pragma unroll
    for (int e = 0; e < NE; e++) {
        float4 wv = ((const float4*)(rw + (size_t)e * D_DIM))[tid];
        red[tid][e] = xa.x * wv.x + xa.y * wv.y + xa.z * wv.z + xa.w * wv.w;
    }
    __syncthreads();
    for (int s = 128; s > 0; s >>= 1) {
        if (tid < s)
#pragma unroll
            for (int e = 0; e < NE; e++) red[tid][e] += red[tid + s][e];
        __syncthreads();
    }
    if (tid == 0) {
        float bv = red[0][0]; int be = 0;
#pragma unroll
        for (int e = 1; e < NE; e++) if (red[0][e] > bv) { bv = red[0][e]; be = e; }
        g_tok_e[t] = be;
        g_tok_s[t] = 1.0f / (1.0f + expf(-bv));
    }
}

// ---------------- stable rank + offsets ----------------
__global__ void rank_kernel() {
    __shared__ int s_e[T_TOK];
    int tid = threadIdx.x;
    for (int i = tid; i < T_TOK; i += 256) s_e[i] = g_tok_e[i];
    __syncthreads();
    int t = blockIdx.x * 256 + tid;
    int e = s_e[t];
    int r = 0;
#pragma unroll 4
    for (int u = 0; u < T_TOK; u++) {
        int eu = s_e[u];
        r += (eu < e) || (eu == e && u < t);
    }
    g_row[t] = r;
    g_order[r] = t;
    if (blockIdx.x == 0 && tid <= NE) {
        int c = 0;
#pragma unroll 4
        for (int u = 0; u < T_TOK; u++) c += (s_e[u] < tid);
        g_offs[tid] = c;
    }
}

// ---------------- scatter+convert hidden ----------------
__global__ void scatter_convert(const float* __restrict__ x) {
    int t = blockIdx.x, tid = threadIdx.x;
    int r = g_row[t];
    float s = g_tok_s[t];
    float4 v = ((const float4*)(x + (size_t)t * D_DIM))[tid];
    unsigned h0, l0, h1, l1;
    split2(v.x, v.y, h0, l0); split2(v.z, v.w, h1, l1);
    size_t o = ((size_t)t * D_DIM) / 2 + tid * 2;
    ((unsigned*)g_Xh)[o] = h0; ((unsigned*)g_Xh)[o + 1] = h1;
    ((unsigned*)g_Xl)[o] = l0; ((unsigned*)g_Xl)[o + 1] = l1;
    split2(v.x * s, v.y * s, h0, l0); split2(v.z * s, v.w * s, h1, l1);
    size_t o2 = ((size_t)r * D_DIM) / 2 + tid * 2;
    ((unsigned*)g_Xeh)[o2] = h0; ((unsigned*)g_Xeh)[o2 + 1] = h1;
    ((unsigned*)g_Xel)[o2] = l0; ((unsigned*)g_Xel)[o2 + 1] = l1;
}

// ================= gate+up GEMM: 3-stage cp.async pipeline =================
// per-stage layout: Ah@0 (6144B), Al@6144, Gh@12288 (2304B), Gl@14592, Uh@16896, Ul@19200
#define GU_STG 21504
#define GU_SMEM_BYTES (3 * GU_STG)

__global__ void __launch_bounds__(256, 2)
gemm_gateup_all(const float* __restrict__ w_gate, const float* __restrict__ w_up) {
    const int BK = 16, LDA = 24, LDB = 72;
    const int K = D_DIM, N = F_DIM;
    extern __shared__ __align__(16) char dsm[];

    int z = blockIdx.z;
    bool routed = (z > 0);
    int e = z - 1;
    int seg_start = 0, seg_rows = T_TOK;
    const __nv_bfloat16 *Ah, *Al;
    __nv_bfloat16 *Hh, *Hl;
    const float *Gf = nullptr, *Uf = nullptr;
    const __nv_bfloat16 *Gp = nullptr, *Glp = nullptr, *Up = nullptr, *Ulp = nullptr;
    if (routed) {
        seg_start = g_offs[e]; seg_rows = g_offs[e + 1] - seg_start;
        Ah = g_Xeh; Al = g_Xel;
        Gf = w_gate + (size_t)e * D_DIM * F_DIM;
        Uf = w_up   + (size_t)e * D_DIM * F_DIM;
        Hh = g_H2h; Hl = g_H2l;
    } else {
        Ah = g_Xh; Al = g_Xl;
        Gp = g_sWgh; Glp = g_sWgl; Up = g_sWuh; Ulp = g_sWul;
        Hh = g_Hh; Hl = g_Hl;
    }
    int row0 = blockIdx.y * 128;
    if (row0 >= seg_rows) return;
    int col0 = blockIdx.x * 64;

    int tid = threadIdx.x, lane = tid & 31, wid = tid >> 5;
    int wm = wid & 3, wn = wid >> 2;

    auto pA = [&](int st, int pl) { return (__nv_bfloat16*)(dsm + st * GU_STG + pl * 6144); };
    auto pB = [&](int st, int pl) { return (__nv_bfloat16*)(dsm + st * GU_STG + 12288 + pl * 2304); };

    // A staging (planes; clamped rows, invalid rows discarded in epilogue)
    int arow = tid >> 1, ak8 = (tid & 1) * 8;
    int arc = row0 + arow; if (arc >= seg_rows) arc = 0;
    const __nv_bfloat16* aph = Ah + (size_t)(seg_start + arc) * K + ak8;
    const __nv_bfloat16* apl = Al + (size_t)(seg_start + arc) * K + ak8;

    // B staging (shared path: 4 planes via cp.async)
    int bpl = tid >> 6, bsub = tid & 63;
    int brow = bsub >> 3, bch = (bsub & 7) * 8;
    const __nv_bfloat16* bsrc = (bpl == 0) ? Gp : (bpl == 1) ? Glp : (bpl == 2) ? Up : Ulp;
    const __nv_bfloat16* bp0 = routed ? nullptr : bsrc + (size_t)brow * N + col0 + bch;
    const __nv_bfloat16* bp1 = routed ? nullptr : bsrc + (size_t)(brow + 8) * N + col0 + bch;

    // B staging (routed path: fp32 + in-kernel split)
    int bkr = tid >> 4, bcc = (tid & 15) * 4;
    const float* gp = routed ? Gf + (size_t)bkr * N + col0 + bcc : nullptr;
    const float* up = routed ? Uf + (size_t)bkr * N + col0 + bcc : nullptr;

    float accg[2][4][4] = {}, accu[2][4][4] = {};

    auto stage_async = [&](int st, int tile) {
        cpa16(pA(st, 0) + arow * LDA + ak8, aph + tile * BK);
        cpa16(pA(st, 1) + arow * LDA + ak8, apl + tile * BK);
        if (!routed) {
            __nv_bfloat16* sB = pB(st, bpl);
            cpa16(sB + brow * LDB + bch, bp0 + (size_t)tile * BK * N);
            cpa16(sB + (brow + 8) * LDB + bch, bp1 + (size_t)tile * BK * N);
        }
        cpa_commit();
    };
    auto store_routedB = [&](int st, float4 gv, float4 uv) {
        unsigned h0, l0, h1, l1;
        int off = bkr * LDB + bcc;
        split2(gv.x, gv.y, h0, l0); split2(gv.z, gv.w, h1, l1);
        *(unsigned*)(pB(st, 0) + off) = h0; *(unsigned*)(pB(st, 0) + off + 2) = h1;
        *(unsigned*)(pB(st, 1) + off) = l0; *(unsigned*)(pB(st, 1) + off + 2) = l1;
        split2(uv.x, uv.y, h0, l0); split2(uv.z, uv.w, h1, l1);
        *(unsigned*)(pB(st, 2) + off) = h0; *(unsigned*)(pB(st, 2) + off + 2) = h1;
        *(unsigned*)(pB(st, 3) + off) = l0; *(unsigned*)(pB(st, 3) + off + 2) = l1;
    };

    auto compute = [&](int st) {
        unsigned ah[2][4], al[2][4];
        const __nv_bfloat16* sAh = pA(st, 0);
        const __nv_bfloat16* sAl = pA(st, 1);
#pragma unroll
        for (int mt = 0; mt < 2; mt++) {
            int r = wm * 32 + mt * 16 + (lane & 15);
            int kk = (lane >> 4) * 8;
            ldsm4(ah[mt], sAh + r * LDA + kk);
            ldsm4(al[mt], sAl + r * LDA + kk);
        }
#pragma unroll
        for (int h = 0; h < 2; h++) {
            int krow = lane & 15;
            int nof = wn * 32 + h * 16 + (lane >> 4) * 8;
            unsigned gh[4], gl[4], uh[4], ul[4];
            ldsm4t(gh, pB(st, 0) + krow * LDB + nof);
            ldsm4t(gl, pB(st, 1) + krow * LDB + nof);
            ldsm4t(uh, pB(st, 2) + krow * LDB + nof);
            ldsm4t(ul, pB(st, 3) + krow * LDB + nof);
#pragma unroll
            for (int mt = 0; mt < 2; mt++)
#pragma unroll
                for (int nn = 0; nn < 2; nn++) {
                    float* cg = accg[mt][h * 2 + nn];
                    float* cu = accu[mt][h * 2 + nn];
                    mma_bf16(cg, ah[mt], gh[2*nn], gh[2*nn+1]);
                    mma_bf16(cg, ah[mt], gl[2*nn], gl[2*nn+1]);
                    mma_bf16(cg, al[mt], gh[2*nn], gh[2*nn+1]);
                    mma_bf16(cu, ah[mt], uh[2*nn], uh[2*nn+1]);
                    mma_bf16(cu, ah[mt], ul[2*nn], ul[2*nn+1]);
                    mma_bf16(cu, al[mt], uh[2*nn], uh[2*nn+1]);
                }
        }
    };

    const int nC = K / BK;   // 64
    // prologue: stages 0 and 1 in flight
    stage_async(0, 0);
    if (routed) store_routedB(0, *(const float4*)gp, *(const float4*)up);
    stage_async(1, 1);
    cpa_wait<1>();           // stage 0 loads complete
    __syncthreads();

    for (int t = 0; t < nC; t++) {
        int st = t % 3;
        bool have1 = (t + 1) < nC, have2 = (t + 2) < nC;
        if (have2) stage_async((t + 2) % 3, t + 2);
        float4 gv, uv;
        if (routed && have1) {
            gv = *(const float4*)(gp + (size_t)(t + 1) * BK * N);
            uv = *(const float4*)(up + (size_t)(t + 1) * BK * N);
        }
        compute(st);
        if (routed && have1) store_routedB((t + 1) % 3, gv, uv);
        if (have2)      cpa_wait<1>();
        else if (have1) cpa_wait<0>();
        __syncthreads();
    }

    // epilogue: H = silu(g)*u -> bf16 planes
    __nv_bfloat16* Hhs = Hh + (size_t)seg_start * N;
    __nv_bfloat16* Hls = Hl + (size_t)seg_start * N;
#pragma unroll
    for (int mt = 0; mt < 2; mt++)
#pragma unroll
        for (int nn = 0; nn < 4; nn++) {
            int r0 = row0 + wm * 32 + mt * 16 + (lane >> 2);
            int c = col0 + wn * 32 + nn * 8 + (lane & 3) * 2;
            float* cg = accg[mt][nn]; float* cu = accu[mt][nn];
            if (r0 < seg_rows) {
                unsigned h, l;
                split2(silu_f(cg[0]) * cu[0], silu_f(cg[1]) * cu[1], h, l);
                ((unsigned*)Hhs)[((size_t)r0 * N + c) >> 1] = h;
                ((unsigned*)Hls)[((size_t)r0 * N + c) >> 1] = l;
            }
            int r1 = r0 + 8;
            if (r1 < seg_rows) {
                unsigned h, l;
                split2(silu_f(cg[2]) * cu[2], silu_f(cg[3]) * cu[3], h, l);
                ((unsigned*)Hhs)[((size_t)r1 * N + c) >> 1] = h;
                ((unsigned*)Hls)[((size_t)r1 * N + c) >> 1] = l;
            }
        }
}

// ================= down GEMM: 3-stage cp.async pipeline =================
// per-stage layout: Ah@0 (6144B), Al@6144, Bh@12288 (4352B), Bl@16640
#define DN_STG 20992
#define DN_SMEM_BYTES (3 * DN_STG)

__global__ void __launch_bounds__(256, 2)
gemm_down_all(float* __restrict__ out, const float* __restrict__ w_down) {
    const int BK = 16, LDA = 24, LDB = 136;
    const int K = F_DIM, N = D_DIM;
    extern __shared__ __align__(16) char dsm[];

    int z = blockIdx.z;
    bool routed = (z > 0);
    int e = z - 1;
    int seg_start = 0, seg_rows = T_TOK;
    const __nv_bfloat16 *Ah, *Al, *Bh = nullptr, *Bl = nullptr;
    const float* Bf = nullptr;
    if (routed) {
        seg_start = g_offs[e]; seg_rows = g_offs[e + 1] - seg_start;
        Ah = g_H2h; Al = g_H2l;
        Bf = w_down + (size_t)e * F_DIM * D_DIM;
    } else {
        Ah = g_Hh; Al = g_Hl; Bh = g_sWdh; Bl = g_sWdl;
    }
    int row0 = blockIdx.y * 128;
    if (row0 >= seg_rows) return;
    int col0 = blockIdx.x * 128;

    int tid = threadIdx.x, lane = tid & 31, wid = tid >> 5;
    int wm = wid & 3, wn = wid >> 2;

    auto pA = [&](int st, int pl) { return (__nv_bfloat16*)(dsm + st * DN_STG + pl * 6144); };
    auto pB = [&](int st, int pl) { return (__nv_bfloat16*)(dsm + st * DN_STG + 12288 + pl * 4352); };

    int arow = tid >> 1, ak8 = (tid & 1) * 8;
    int arc = row0 + arow; if (arc >= seg_rows) arc = 0;
    const __nv_bfloat16* aph = Ah + (size_t)(seg_start + arc) * K + ak8;
    const __nv_bfloat16* apl = Al + (size_t)(seg_start + arc) * K + ak8;

    int bplq = tid >> 7, bsub = tid & 127;
    int brow = bsub >> 4, bch = (bsub & 15) * 8;
    const __nv_bfloat16* bsrc = bplq ? Bl : Bh;
    const __nv_bfloat16* bp0 = routed ? nullptr : bsrc + (size_t)brow * N + col0 + bch;
    const __nv_bfloat16* bp1 = routed ? nullptr : bsrc + (size_t)(brow + 8) * N + col0 + bch;

    int bkr[2], bcc[2]; const float* bp[2] = { nullptr, nullptr };
#pragma unroll
    for (int i = 0; i < 2; i++) {
        int f4 = i * 256 + tid;
        bkr[i] = f4 >> 5; bcc[i] = (f4 & 31) * 4;
        if (routed) bp[i] = Bf + (size_t)bkr[i] * N + col0 + bcc[i];
    }

    float acc[2][8][4] = {};

    auto stage_async = [&](int st, int tile) {
        cpa16(pA(st, 0) + arow * LDA + ak8, aph + tile * BK);
        cpa16(pA(st, 1) + arow * LDA + ak8, apl + tile * BK);
        if (!routed) {
            __nv_bfloat16* sB = pB(st, bplq);
            cpa16(sB + brow * LDB + bch, bp0 + (size_t)tile * BK * N);
            cpa16(sB + (brow + 8) * LDB + bch, bp1 + (size_t)tile * BK * N);
        }
        cpa_commit();
    };
    auto store_routedB = [&](int st, const float4 bv[2]) {
#pragma unroll
        for (int i = 0; i < 2; i++) {
            unsigned h0, l0, h1, l1;
            split2(bv[i].x, bv[i].y, h0, l0); split2(bv[i].z, bv[i].w, h1, l1);
            int off = bkr[i] * LDB + bcc[i];
            *(unsigned*)(pB(st, 0) + off) = h0; *(unsigned*)(pB(st, 0) + off + 2) = h1;
            *(unsigned*)(pB(st, 1) + off) = l0; *(unsigned*)(pB(st, 1) + off + 2) = l1;
        }
    };

    auto compute = [&](int st) {
        unsigned ah[2][4], al[2][4];
        const __nv_bfloat16* sAh = pA(st, 0);
        const __nv_bfloat16* sAl = pA(st, 1);
#pragma unroll
        for (int mt = 0; mt < 2; mt++) {
            int r = wm * 32 + mt * 16 + (lane & 15);
            int kk = (lane >> 4) * 8;
            ldsm4(ah[mt], sAh + r * LDA + kk);
            ldsm4(al[mt], sAl + r * LDA + kk);
        }
#pragma unroll
        for (int h = 0; h < 4; h++) {
            int krow = lane & 15;
            int nof = wn * 64 + h * 16 + (lane >> 4) * 8;
            unsigned bh[4], bl[4];
            ldsm4t(bh, pB(st, 0) + krow * LDB + nof);
            ldsm4t(bl, pB(st, 1) + krow * LDB + nof);
#pragma unroll
            for (int mt = 0; mt < 2; mt++)
#pragma unroll
                for (int nn = 0; nn < 2; nn++) {
                    float* c = acc[mt][h * 2 + nn];
                    mma_bf16(c, ah[mt], bh[2*nn], bh[2*nn+1]);
                    mma_bf16(c, ah[mt], bl[2*nn], bl[2*nn+1]);
                    mma_bf16(c, al[mt], bh[2*nn], bh[2*nn+1]);
                }
        }
    };

    const int nC = K / BK;   // 128
    stage_async(0, 0);
    if (routed) {
        float4 bv0[2] = { *(const float4*)bp[0], *(const float4*)bp[1] };
        store_routedB(0, bv0);
    }
    stage_async(1, 1);
    cpa_wait<1>();
    __syncthreads();

    for (int t = 0; t < nC; t++) {
        int st = t % 3;
        bool have1 = (t + 1) < nC, have2 = (t + 2) < nC;
        if (have2) stage_async((t + 2) % 3, t + 2);
        float4 bv[2];
        if (routed && have1) {
            bv[0] = *(const float4*)(bp[0] + (size_t)(t + 1) * BK * N);
            bv[1] = *(const float4*)(bp[1] + (size_t)(t + 1) * BK * N);
        }
        compute(st);
        if (routed && have1) store_routedB((t + 1) % 3, bv);
        if (have2)      cpa_wait<1>();
        else if (have1) cpa_wait<0>();
        __syncthreads();
    }

#pragma unroll
    for (int mt = 0; mt < 2; mt++) {
        int rb0 = row0 + wm * 32 + mt * 16 + (lane >> 2);
        int rb1 = rb0 + 8;
        int tok0 = -1, tok1 = -1;
        if (rb0 < seg_rows) tok0 = routed ? g_order[seg_start + rb0] : rb0;
        if (rb1 < seg_rows) tok1 = routed ? g_order[seg_start + rb1] : rb1;
        float* dst = routed ? g_O2 : out;
#pragma unroll
        for (int nn = 0; nn < 8; nn++) {
            int c = col0 + wn * 64 + nn * 8 + (lane & 3) * 2;
            float* cc = acc[mt][nn];
            if (tok0 >= 0) { float2 v = { cc[0], cc[1] }; *(float2*)&dst[(size_t)tok0 * N + c] = v; }
            if (tok1 >= 0) { float2 v = { cc[2], cc[3] }; *(float2*)&dst[(size_t)tok1 * N + c] = v; }
        }
    }
}

// ---------------- final add ----------------
__global__ void add_kernel(float* __restrict__ out) {
    size_t i = (size_t)blockIdx.x * 256 + threadIdx.x;
    float4 v = ((float4*)out)[i];
    float4 w = ((const float4*)g_O2)[i];
    v.x += w.x; v.y += w.y; v.z += w.z; v.w += w.w;
    ((float4*)out)[i] = v;
}

extern "C" void kernel_launch(void* const* d_in, const int* in_sizes, int n_in,
                              void* d_out, int out_size) {
    const float* hidden   = (const float*)d_in[0];
    const float* router_w = (const float*)d_in[1];
    const float* w_gate   = (const float*)d_in[2];
    const float* w_up     = (const float*)d_in[3];
    const float* w_down   = (const float*)d_in[4];
    const float* ws_gate  = (const float*)d_in[5];
    const float* ws_up    = (const float*)d_in[6];
    const float* ws_down  = (const float*)d_in[7];
    float* out = (float*)d_out;

    cudaFuncSetAttribute(gemm_gateup_all, cudaFuncAttributeMaxDynamicSharedMemorySize, GU_SMEM_BYTES);
    cudaFuncSetAttribute(gemm_down_all,   cudaFuncAttributeMaxDynamicSharedMemorySize, DN_SMEM_BYTES);

    conv_shared<<<512, 256>>>(ws_gate, ws_up, ws_down);
    router_kernel<<<T_TOK, 256>>>(hidden, router_w);
    rank_kernel<<<T_TOK / 256, 256>>>();
    scatter_convert<<<T_TOK, 256>>>(hidden);

    dim3 gridGU(F_DIM / 64, T_TOK / 128, NE + 1);
    gemm_gateup_all<<<gridGU, 256, GU_SMEM_BYTES>>>(w_gate, w_up);
    dim3 gridDN(D_DIM / 128, T_TOK / 128, NE + 1);
    gemm_down_all<<<gridDN, 256, DN_SMEM_BYTES>>>(out, w_down);
    add_kernel<<<(T_TOK * D_DIM / 4) / 256, 256>>>(out);

    (void)in_sizes; (void)n_in; (void)out_size;
}

// round 13
// speedup vs baseline: 1.3432x; 1.3432x over previous
#include <cuda_runtime.h>
#include <cuda_fp16.h>
#include <cstdint>
#include <math.h>

#define T_TOK 2048
#define D_DIM 1024
#define F_DIM 2048
#define NE 8

// ---- scratch: referenced ONLY inside device code ----
__device__ __half g_sWg16[(size_t)D_DIM * F_DIM];   // shared weights, single fp16 plane
__device__ __half g_sWu16[(size_t)D_DIM * F_DIM];
__device__ __half g_sWd16[(size_t)F_DIM * D_DIM];
__device__ __half g_Xh [(size_t)T_TOK * D_DIM], g_Xl [(size_t)T_TOK * D_DIM]; // hidden fp16 hi/lo (token order)
__device__ __half g_Xeh[(size_t)T_TOK * D_DIM], g_Xel[(size_t)T_TOK * D_DIM]; // scaled fp16 hi/lo (grouped)
__device__ __half g_Hh [(size_t)T_TOK * F_DIM], g_Hl [(size_t)T_TOK * F_DIM]; // shared H fp16 hi/lo
__device__ __half g_H2h[(size_t)T_TOK * F_DIM], g_H2l[(size_t)T_TOK * F_DIM]; // routed H fp16 hi/lo
__device__ float g_O2[(size_t)T_TOK * D_DIM];
__device__ int   g_tok_e[T_TOK];
__device__ float g_tok_s[T_TOK];
__device__ int   g_row[T_TOK];
__device__ int   g_order[T_TOK];
__device__ int   g_offs[NE + 1];

__device__ __forceinline__ float silu_f(float x) { return x / (1.0f + expf(-x)); }

// fp16 split: x = hi + lo, both fp16; packs pairs into fp16x2 words
__device__ __forceinline__ void splith2(float x0, float x1, unsigned &hi, unsigned &lo) {
    __half h0 = __float2half_rn(x0), h1 = __float2half_rn(x1);
    hi = (unsigned)__half_as_ushort(h0) | ((unsigned)__half_as_ushort(h1) << 16);
    lo = (unsigned)__half_as_ushort(__float2half_rn(x0 - __half2float(h0)))
       | ((unsigned)__half_as_ushort(__float2half_rn(x1 - __half2float(h1))) << 16);
}
__device__ __forceinline__ unsigned cvt2(float x0, float x1) {
    return (unsigned)__half_as_ushort(__float2half_rn(x0))
         | ((unsigned)__half_as_ushort(__float2half_rn(x1)) << 16);
}

__device__ __forceinline__ void cpa16(void* smem, const void* gmem) {
    unsigned s = (unsigned)__cvta_generic_to_shared(smem);
    asm volatile("cp.async.cg.shared.global [%0], [%1], 16;" :: "r"(s), "l"(gmem));
}
__device__ __forceinline__ void cpa_commit() { asm volatile("cp.async.commit_group;"); }
__device__ __forceinline__ void cpa_wait_all() { asm volatile("cp.async.wait_group 0;" ::: "memory"); }

__device__ __forceinline__ void ldsm4(unsigned r[4], const void* p) {
    unsigned a = (unsigned)__cvta_generic_to_shared(p);
    asm volatile("ldmatrix.sync.aligned.m8n8.x4.shared.b16 {%0,%1,%2,%3}, [%4];"
                 : "=r"(r[0]), "=r"(r[1]), "=r"(r[2]), "=r"(r[3]) : "r"(a));
}
__device__ __forceinline__ void ldsm4t(unsigned r[4], const void* p) {
    unsigned a = (unsigned)__cvta_generic_to_shared(p);
    asm volatile("ldmatrix.sync.aligned.m8n8.x4.trans.shared.b16 {%0,%1,%2,%3}, [%4];"
                 : "=r"(r[0]), "=r"(r[1]), "=r"(r[2]), "=r"(r[3]) : "r"(a));
}
__device__ __forceinline__ void mma_f16(float c[4], const unsigned a[4], unsigned b0, unsigned b1) {
    asm volatile(
        "mma.sync.aligned.m16n8k16.row.col.f32.f16.f16.f32 "
        "{%0,%1,%2,%3}, {%4,%5,%6,%7}, {%8,%9}, {%0,%1,%2,%3};"
        : "+f"(c[0]), "+f"(c[1]), "+f"(c[2]), "+f"(c[3])
        : "r"(a[0]), "r"(a[1]), "r"(a[2]), "r"(a[3]), "r"(b0), "r"(b1));
}

// ---------------- convert shared weights: fp32 -> single fp16 plane ----------------
__global__ void conv_shared(const float* __restrict__ g, const float* __restrict__ u,
                            const float* __restrict__ d) {
    const int n4 = D_DIM * F_DIM / 4;
    for (int idx = blockIdx.x * 256 + threadIdx.x; idx < 3 * n4; idx += gridDim.x * 256) {
        int which = idx / n4, i = idx - which * n4;
        const float* src = (which == 0) ? g : (which == 1) ? u : d;
        __half* dst = (which == 0) ? g_sWg16 : (which == 1) ? g_sWu16 : g_sWd16;
        float4 v = ((const float4*)src)[i];
        ((unsigned*)dst)[2 * i]     = cvt2(v.x, v.y);
        ((unsigned*)dst)[2 * i + 1] = cvt2(v.z, v.w);
    }
}

// ---------------- router ----------------
__global__ void router_kernel(const float* __restrict__ x, const float* __restrict__ rw) {
    __shared__ float red[256][NE + 1];
    int t = blockIdx.x, tid = threadIdx.x;
    float4 xa = ((const float4*)(x + (size_t)t * D_DIM))[tid];
#pragma unroll
    for (int e = 0; e < NE; e++) {
        float4 wv = ((const float4*)(rw + (size_t)e * D_DIM))[tid];
        red[tid][e] = xa.x * wv.x + xa.y * wv.y + xa.z * wv.z + xa.w * wv.w;
    }
    __syncthreads();
    for (int s = 128; s > 0; s >>= 1) {
        if (tid < s)
#pragma unroll
            for (int e = 0; e < NE; e++) red[tid][e] += red[tid + s][e];
        __syncthreads();
    }
    if (tid == 0) {
        float bv = red[0][0]; int be = 0;
#pragma unroll
        for (int e = 1; e < NE; e++) if (red[0][e] > bv) { bv = red[0][e]; be = e; }
        g_tok_e[t] = be;
        g_tok_s[t] = 1.0f / (1.0f + expf(-bv));
    }
}

// ---------------- stable rank + offsets ----------------
__global__ void rank_kernel() {
    __shared__ int s_e[T_TOK];
    int tid = threadIdx.x;
    for (int i = tid; i < T_TOK; i += 256) s_e[i] = g_tok_e[i];
    __syncthreads();
    int t = blockIdx.x * 256 + tid;
    int e = s_e[t];
    int r = 0;
#pragma unroll 4
    for (int u = 0; u < T_TOK; u++) {
        int eu = s_e[u];
        r += (eu < e) || (eu == e && u < t);
    }
    g_row[t] = r;
    g_order[r] = t;
    if (blockIdx.x == 0 && tid <= NE) {
        int c = 0;
#pragma unroll 4
        for (int u = 0; u < T_TOK; u++) c += (s_e[u] < tid);
        g_offs[tid] = c;
    }
}

// ---------------- scatter+convert hidden (fp16 hi/lo) ----------------
__global__ void scatter_convert(const float* __restrict__ x) {
    int t = blockIdx.x, tid = threadIdx.x;
    int r = g_row[t];
    float s = g_tok_s[t];
    float4 v = ((const float4*)(x + (size_t)t * D_DIM))[tid];
    unsigned h0, l0, h1, l1;
    splith2(v.x, v.y, h0, l0); splith2(v.z, v.w, h1, l1);
    size_t o = ((size_t)t * D_DIM) / 2 + tid * 2;
    ((unsigned*)g_Xh)[o] = h0; ((unsigned*)g_Xh)[o + 1] = h1;
    ((unsigned*)g_Xl)[o] = l0; ((unsigned*)g_Xl)[o + 1] = l1;
    splith2(v.x * s, v.y * s, h0, l0); splith2(v.z * s, v.w * s, h1, l1);
    size_t o2 = ((size_t)r * D_DIM) / 2 + tid * 2;
    ((unsigned*)g_Xeh)[o2] = h0; ((unsigned*)g_Xeh)[o2 + 1] = h1;
    ((unsigned*)g_Xel)[o2] = l0; ((unsigned*)g_Xel)[o2 + 1] = l1;
}

// ================= gate+up GEMM: A fp16 hi/lo (2 MMAs), B single fp16 plane =================
__global__ void __launch_bounds__(256, 2)
gemm_gateup_all(const float* __restrict__ w_gate, const float* __restrict__ w_up) {
    const int BK = 16, LDA = 24, LDB = 72;
    const int K = D_DIM, N = F_DIM;

    int z = blockIdx.z;
    bool routed = (z > 0);
    int e = z - 1;
    int seg_start = 0, seg_rows = T_TOK;
    const __half *Ah, *Al;
    __half *Hh, *Hl;
    const float *Gf = nullptr, *Uf = nullptr;
    const __half *Gp = nullptr, *Upp = nullptr;
    if (routed) {
        seg_start = g_offs[e]; seg_rows = g_offs[e + 1] - seg_start;
        Ah = g_Xeh; Al = g_Xel;
        Gf = w_gate + (size_t)e * D_DIM * F_DIM;
        Uf = w_up   + (size_t)e * D_DIM * F_DIM;
        Hh = g_H2h; Hl = g_H2l;
    } else {
        Ah = g_Xh; Al = g_Xl;
        Gp = g_sWg16; Upp = g_sWu16;
        Hh = g_Hh; Hl = g_Hl;
    }
    int row0 = blockIdx.y * 128;
    if (row0 >= seg_rows) return;
    int col0 = blockIdx.x * 64;

    __shared__ __align__(16) __half sAh[2][128 * LDA], sAl[2][128 * LDA];
    __shared__ __align__(16) __half sG[2][BK * LDB], sU[2][BK * LDB];

    int tid = threadIdx.x, lane = tid & 31, wid = tid >> 5;
    int wm = wid & 3, wn = wid >> 2;

    // A staging (fp16 planes via cp.async; clamped rows discarded in epilogue)
    int arow = tid >> 1, ak8 = (tid & 1) * 8;
    int arc = row0 + arow; if (arc >= seg_rows) arc = 0;
    const __half* aph = Ah + (size_t)(seg_start + arc) * K + ak8;
    const __half* apl = Al + (size_t)(seg_start + arc) * K + ak8;

    // B staging, shared path: 2 planes x 128 slots (16 rows x 8 chunks), 1 cpa16/thread
    int bpl = tid >> 7, bsub = tid & 127;
    int brow = bsub >> 3, bch = (bsub & 7) * 8;
    const __half* bsrc = bpl ? Upp : Gp;
    const __half* bp0 = routed ? nullptr : bsrc + (size_t)brow * N + col0 + bch;

    // B staging, routed path: fp32 + cvt (one float4/thread per matrix)
    int bkr = tid >> 4, bcc = (tid & 15) * 4;
    const float* gp = routed ? Gf + (size_t)bkr * N + col0 + bcc : nullptr;
    const float* up = routed ? Uf + (size_t)bkr * N + col0 + bcc : nullptr;

    float accg[2][4][4] = {}, accu[2][4][4] = {};

    auto stage_async = [&](int buf, int tile) {
        cpa16(&sAh[buf][arow * LDA + ak8], aph + tile * BK);
        cpa16(&sAl[buf][arow * LDA + ak8], apl + tile * BK);
        if (!routed) {
            __half* sB = bpl ? &sU[buf][0] : &sG[buf][0];
            cpa16(sB + brow * LDB + bch, bp0 + (size_t)tile * BK * N);
        }
        cpa_commit();
    };
    auto store_routedB = [&](int buf, float4 gv, float4 uv) {
        int off = bkr * LDB + bcc;
        *(unsigned*)&sG[buf][off]     = cvt2(gv.x, gv.y);
        *(unsigned*)&sG[buf][off + 2] = cvt2(gv.z, gv.w);
        *(unsigned*)&sU[buf][off]     = cvt2(uv.x, uv.y);
        *(unsigned*)&sU[buf][off + 2] = cvt2(uv.z, uv.w);
    };

    auto compute = [&](int buf) {
        unsigned ah[2][4], al[2][4];
#pragma unroll
        for (int mt = 0; mt < 2; mt++) {
            int r = wm * 32 + mt * 16 + (lane & 15);
            int kk = (lane >> 4) * 8;
            ldsm4(ah[mt], &sAh[buf][r * LDA + kk]);
            ldsm4(al[mt], &sAl[buf][r * LDA + kk]);
        }
#pragma unroll
        for (int h = 0; h < 2; h++) {
            int krow = lane & 15;
            int nof = wn * 32 + h * 16 + (lane >> 4) * 8;
            unsigned gg[4], uu[4];
            ldsm4t(gg, &sG[buf][krow * LDB + nof]);
            ldsm4t(uu, &sU[buf][krow * LDB + nof]);
#pragma unroll
            for (int mt = 0; mt < 2; mt++)
#pragma unroll
                for (int nn = 0; nn < 2; nn++) {
                    float* cg = accg[mt][h * 2 + nn];
                    float* cu = accu[mt][h * 2 + nn];
                    mma_f16(cg, ah[mt], gg[2*nn], gg[2*nn+1]);
                    mma_f16(cg, al[mt], gg[2*nn], gg[2*nn+1]);
                    mma_f16(cu, ah[mt], uu[2*nn], uu[2*nn+1]);
                    mma_f16(cu, al[mt], uu[2*nn], uu[2*nn+1]);
                }
        }
    };

    const int nC = K / BK;
    stage_async(0, 0);
    if (routed) store_routedB(0, *(const float4*)gp, *(const float4*)up);
    cpa_wait_all();
    __syncthreads();

    for (int t = 0; t < nC; t++) {
        int buf = t & 1;
        bool more = (t + 1) < nC;
        float4 gv, uv;
        if (more) {
            stage_async(buf ^ 1, t + 1);
            if (routed) {
                gv = *(const float4*)(gp + (size_t)(t + 1) * BK * N);
                uv = *(const float4*)(up + (size_t)(t + 1) * BK * N);
            }
        }
        compute(buf);
        if (more) {
            if (routed) store_routedB(buf ^ 1, gv, uv);
            cpa_wait_all();
        }
        __syncthreads();
    }

    // epilogue: H = silu(g)*u -> fp16 hi/lo planes
    __half* Hhs = Hh + (size_t)seg_start * N;
    __half* Hls = Hl + (size_t)seg_start * N;
#pragma unroll
    for (int mt = 0; mt < 2; mt++)
#pragma unroll
        for (int nn = 0; nn < 4; nn++) {
            int r0 = row0 + wm * 32 + mt * 16 + (lane >> 2);
            int c = col0 + wn * 32 + nn * 8 + (lane & 3) * 2;
            float* cg = accg[mt][nn]; float* cu = accu[mt][nn];
            if (r0 < seg_rows) {
                unsigned h, l;
                splith2(silu_f(cg[0]) * cu[0], silu_f(cg[1]) * cu[1], h, l);
                ((unsigned*)Hhs)[((size_t)r0 * N + c) >> 1] = h;
                ((unsigned*)Hls)[((size_t)r0 * N + c) >> 1] = l;
            }
            int r1 = r0 + 8;
            if (r1 < seg_rows) {
                unsigned h, l;
                splith2(silu_f(cg[2]) * cu[2], silu_f(cg[3]) * cu[3], h, l);
                ((unsigned*)Hhs)[((size_t)r1 * N + c) >> 1] = h;
                ((unsigned*)Hls)[((size_t)r1 * N + c) >> 1] = l;
            }
        }
}

// ================= down GEMM: A fp16 hi/lo (2 MMAs), B single fp16 plane =================
__global__ void __launch_bounds__(256, 2)
gemm_down_all(float* __restrict__ out, const float* __restrict__ w_down) {
    const int BK = 16, LDA = 24, LDB = 136;
    const int K = F_DIM, N = D_DIM;

    int z = blockIdx.z;
    bool routed = (z > 0);
    int e = z - 1;
    int seg_start = 0, seg_rows = T_TOK;
    const __half *Ah, *Al, *Bp = nullptr;
    const float* Bf = nullptr;
    if (routed) {
        seg_start = g_offs[e]; seg_rows = g_offs[e + 1] - seg_start;
        Ah = g_H2h; Al = g_H2l;
        Bf = w_down + (size_t)e * F_DIM * D_DIM;
    } else {
        Ah = g_Hh; Al = g_Hl; Bp = g_sWd16;
    }
    int row0 = blockIdx.y * 128;
    if (row0 >= seg_rows) return;
    int col0 = blockIdx.x * 128;

    __shared__ __align__(16) __half sAh[2][128 * LDA], sAl[2][128 * LDA];
    __shared__ __align__(16) __half sB[2][BK * LDB];

    int tid = threadIdx.x, lane = tid & 31, wid = tid >> 5;
    int wm = wid & 3, wn = wid >> 2;

    int arow = tid >> 1, ak8 = (tid & 1) * 8;
    int arc = row0 + arow; if (arc >= seg_rows) arc = 0;
    const __half* aph = Ah + (size_t)(seg_start + arc) * K + ak8;
    const __half* apl = Al + (size_t)(seg_start + arc) * K + ak8;

    // shared B: 16 rows x 16 chunks = 256 slots, 1 cpa16/thread
    int brow = tid >> 4, bch = (tid & 15) * 8;
    const __half* bp0 = routed ? nullptr : Bp + (size_t)brow * N + col0 + bch;

    // routed B fp32: 2 float4/thread -> cvt
    int bkr[2], bcc[2]; const float* bp[2] = { nullptr, nullptr };
#pragma unroll
    for (int i = 0; i < 2; i++) {
        int f4 = i * 256 + tid;
        bkr[i] = f4 >> 5; bcc[i] = (f4 & 31) * 4;
        if (routed) bp[i] = Bf + (size_t)bkr[i] * N + col0 + bcc[i];
    }

    float acc[2][8][4] = {};

    auto stage_async = [&](int buf, int tile) {
        cpa16(&sAh[buf][arow * LDA + ak8], aph + tile * BK);
        cpa16(&sAl[buf][arow * LDA + ak8], apl + tile * BK);
        if (!routed) cpa16(&sB[buf][brow * LDB + bch], bp0 + (size_t)tile * BK * N);
        cpa_commit();
    };
    auto store_routedB = [&](int buf, const float4 bv[2]) {
#pragma unroll
        for (int i = 0; i < 2; i++) {
            int off = bkr[i] * LDB + bcc[i];
            *(unsigned*)&sB[buf][off]     = cvt2(bv[i].x, bv[i].y);
            *(unsigned*)&sB[buf][off + 2] = cvt2(bv[i].z, bv[i].w);
        }
    };

    auto compute = [&](int buf) {
        unsigned ah[2][4], al[2][4];
#pragma unroll
        for (int mt = 0; mt < 2; mt++) {
            int r = wm * 32 + mt * 16 + (lane & 15);
            int kk = (lane >> 4) * 8;
            ldsm4(ah[mt], &sAh[buf][r * LDA + kk]);
            ldsm4(al[mt], &sAl[buf][r * LDA + kk]);
        }
#pragma unroll
        for (int h = 0; h < 4; h++) {
            int krow = lane & 15;
            int nof = wn * 64 + h * 16 + (lane >> 4) * 8;
            unsigned bb[4];
            ldsm4t(bb, &sB[buf][krow * LDB + nof]);
#pragma unroll
            for (int mt = 0; mt < 2; mt++)
#pragma unroll
                for (int nn = 0; nn < 2; nn++) {
                    float* c = acc[mt][h * 2 + nn];
                    mma_f16(c, ah[mt], bb[2*nn], bb[2*nn+1]);
                    mma_f16(c, al[mt], bb[2*nn], bb[2*nn+1]);
                }
        }
    };

    const int nC = K / BK;
    stage_async(0, 0);
    if (routed) {
        float4 bv0[2] = { *(const float4*)bp[0], *(const float4*)bp[1] };
        store_routedB(0, bv0);
    }
    cpa_wait_all();
    __syncthreads();

    for (int t = 0; t < nC; t++) {
        int buf = t & 1;
        bool more = (t + 1) < nC;
        float4 bv[2];
        if (more) {
            stage_async(buf ^ 1, t + 1);
            if (routed) {
                bv[0] = *(const float4*)(bp[0] + (size_t)(t + 1) * BK * N);
                bv[1] = *(const float4*)(bp[1] + (size_t)(t + 1) * BK * N);
            }
        }
        compute(buf);
        if (more) {
            if (routed) store_routedB(buf ^ 1, bv);
            cpa_wait_all();
        }
        __syncthreads();
    }

#pragma unroll
    for (int mt = 0; mt < 2; mt++) {
        int rb0 = row0 + wm * 32 + mt * 16 + (lane >> 2);
        int rb1 = rb0 + 8;
        int tok0 = -1, tok1 = -1;
        if (rb0 < seg_rows) tok0 = routed ? g_order[seg_start + rb0] : rb0;
        if (rb1 < seg_rows) tok1 = routed ? g_order[seg_start + rb1] : rb1;
        float* dst = routed ? g_O2 : out;
#pragma unroll
        for (int nn = 0; nn < 8; nn++) {
            int c = col0 + wn * 64 + nn * 8 + (lane & 3) * 2;
            float* cc = acc[mt][nn];
            if (tok0 >= 0) { float2 v = { cc[0], cc[1] }; *(float2*)&dst[(size_t)tok0 * N + c] = v; }
            if (tok1 >= 0) { float2 v = { cc[2], cc[3] }; *(float2*)&dst[(size_t)tok1 * N + c] = v; }
        }
    }
}

// ---------------- final add ----------------
__global__ void add_kernel(float* __restrict__ out) {
    size_t i = (size_t)blockIdx.x * 256 + threadIdx.x;
    float4 v = ((float4*)out)[i];
    float4 w = ((const float4*)g_O2)[i];
    v.x += w.x; v.y += w.y; v.z += w.z; v.w += w.w;
    ((float4*)out)[i] = v;
}

extern "C" void kernel_launch(void* const* d_in, const int* in_sizes, int n_in,
                              void* d_out, int out_size) {
    const float* hidden   = (const float*)d_in[0];
    const float* router_w = (const float*)d_in[1];
    const float* w_gate   = (const float*)d_in[2];
    const float* w_up     = (const float*)d_in[3];
    const float* w_down   = (const float*)d_in[4];
    const float* ws_gate  = (const float*)d_in[5];
    const float* ws_up    = (const float*)d_in[6];
    const float* ws_down  = (const float*)d_in[7];
    float* out = (float*)d_out;

    conv_shared<<<512, 256>>>(ws_gate, ws_up, ws_down);
    router_kernel<<<T_TOK, 256>>>(hidden, router_w);
    rank_kernel<<<T_TOK / 256, 256>>>();
    scatter_convert<<<T_TOK, 256>>>(hidden);

    dim3 gridGU(F_DIM / 64, T_TOK / 128, NE + 1);
    gemm_gateup_all<<<gridGU, 256>>>(w_gate, w_up);
    dim3 gridDN(D_DIM / 128, T_TOK / 128, NE + 1);
    gemm_down_all<<<gridDN, 256>>>(out, w_down);
    add_kernel<<<(T_TOK * D_DIM / 4) / 256, 256>>>(out);

    (void)in_sizes; (void)n_in; (void)out_size;
}

// round 14
// speedup vs baseline: 1.5022x; 1.1184x over previous
#include <cuda_runtime.h>
#include <cuda_fp16.h>
#include <cstdint>
#include <math.h>

#define T_TOK 2048
#define D_DIM 1024
#define F_DIM 2048
#define NE 8

// ---- scratch: referenced ONLY inside device code ----
__device__ __half g_sWg16[(size_t)D_DIM * F_DIM];
__device__ __half g_sWu16[(size_t)D_DIM * F_DIM];
__device__ __half g_sWd16[(size_t)F_DIM * D_DIM];
__device__ __half g_Xh [(size_t)T_TOK * D_DIM], g_Xl [(size_t)T_TOK * D_DIM];
__device__ __half g_Xeh[(size_t)T_TOK * D_DIM], g_Xel[(size_t)T_TOK * D_DIM];
__device__ __half g_Hh [(size_t)T_TOK * F_DIM], g_Hl [(size_t)T_TOK * F_DIM];
__device__ __half g_H2h[(size_t)T_TOK * F_DIM], g_H2l[(size_t)T_TOK * F_DIM];
__device__ float g_O2[(size_t)T_TOK * D_DIM];
__device__ int   g_tok_e[T_TOK];
__device__ float g_tok_s[T_TOK];
__device__ int   g_row[T_TOK];
__device__ int   g_order[T_TOK];
__device__ int   g_offs[NE + 1];

__device__ __forceinline__ float silu_f(float x) { return x / (1.0f + expf(-x)); }

__device__ __forceinline__ void splith2(float x0, float x1, unsigned &hi, unsigned &lo) {
    __half h0 = __float2half_rn(x0), h1 = __float2half_rn(x1);
    hi = (unsigned)__half_as_ushort(h0) | ((unsigned)__half_as_ushort(h1) << 16);
    lo = (unsigned)__half_as_ushort(__float2half_rn(x0 - __half2float(h0)))
       | ((unsigned)__half_as_ushort(__float2half_rn(x1 - __half2float(h1))) << 16);
}
__device__ __forceinline__ unsigned cvt2(float x0, float x1) {
    return (unsigned)__half_as_ushort(__float2half_rn(x0))
         | ((unsigned)__half_as_ushort(__float2half_rn(x1)) << 16);
}

__device__ __forceinline__ void cpa16(void* smem, const void* gmem) {
    unsigned s = (unsigned)__cvta_generic_to_shared(smem);
    asm volatile("cp.async.cg.shared.global [%0], [%1], 16;" :: "r"(s), "l"(gmem));
}
__device__ __forceinline__ void cpa_commit() { asm volatile("cp.async.commit_group;"); }
__device__ __forceinline__ void cpa_wait_all() { asm volatile("cp.async.wait_group 0;" ::: "memory"); }

__device__ __forceinline__ void ldsm4(unsigned r[4], const void* p) {
    unsigned a = (unsigned)__cvta_generic_to_shared(p);
    asm volatile("ldmatrix.sync.aligned.m8n8.x4.shared.b16 {%0,%1,%2,%3}, [%4];"
                 : "=r"(r[0]), "=r"(r[1]), "=r"(r[2]), "=r"(r[3]) : "r"(a));
}
__device__ __forceinline__ void ldsm4t(unsigned r[4], const void* p) {
    unsigned a = (unsigned)__cvta_generic_to_shared(p);
    asm volatile("ldmatrix.sync.aligned.m8n8.x4.trans.shared.b16 {%0,%1,%2,%3}, [%4];"
                 : "=r"(r[0]), "=r"(r[1]), "=r"(r[2]), "=r"(r[3]) : "r"(a));
}
__device__ __forceinline__ void mma_f16(float c[4], const unsigned a[4], unsigned b0, unsigned b1) {
    asm volatile(
        "mma.sync.aligned.m16n8k16.row.col.f32.f16.f16.f32 "
        "{%0,%1,%2,%3}, {%4,%5,%6,%7}, {%8,%9}, {%0,%1,%2,%3};"
        : "+f"(c[0]), "+f"(c[1]), "+f"(c[2]), "+f"(c[3])
        : "r"(a[0]), "r"(a[1]), "r"(a[2]), "r"(a[3]), "r"(b0), "r"(b1));
}

// ---------------- convert shared weights ----------------
__global__ void conv_shared(const float* __restrict__ g, const float* __restrict__ u,
                            const float* __restrict__ d) {
    const int n4 = D_DIM * F_DIM / 4;
    for (int idx = blockIdx.x * 256 + threadIdx.x; idx < 3 * n4; idx += gridDim.x * 256) {
        int which = idx / n4, i = idx - which * n4;
        const float* src = (which == 0) ? g : (which == 1) ? u : d;
        __half* dst = (which == 0) ? g_sWg16 : (which == 1) ? g_sWu16 : g_sWd16;
        float4 v = ((const float4*)src)[i];
        ((unsigned*)dst)[2 * i]     = cvt2(v.x, v.y);
        ((unsigned*)dst)[2 * i + 1] = cvt2(v.z, v.w);
    }
}

// ---------------- router ----------------
__global__ void router_kernel(const float* __restrict__ x, const float* __restrict__ rw) {
    __shared__ float red[256][NE + 1];
    int t = blockIdx.x, tid = threadIdx.x;
    float4 xa = ((const float4*)(x + (size_t)t * D_DIM))[tid];
#pragma unroll
    for (int e = 0; e < NE; e++) {
        float4 wv = ((const float4*)(rw + (size_t)e * D_DIM))[tid];
        red[tid][e] = xa.x * wv.x + xa.y * wv.y + xa.z * wv.z + xa.w * wv.w;
    }
    __syncthreads();
    for (int s = 128; s > 0; s >>= 1) {
        if (tid < s)
#pragma unroll
            for (int e = 0; e < NE; e++) red[tid][e] += red[tid + s][e];
        __syncthreads();
    }
    if (tid == 0) {
        float bv = red[0][0]; int be = 0;
#pragma unroll
        for (int e = 1; e < NE; e++) if (red[0][e] > bv) { bv = red[0][e]; be = e; }
        g_tok_e[t] = be;
        g_tok_s[t] = 1.0f / (1.0f + expf(-bv));
    }
}

// ---------------- stable rank + offsets ----------------
__global__ void rank_kernel() {
    __shared__ int s_e[T_TOK];
    int tid = threadIdx.x;
    for (int i = tid; i < T_TOK; i += 256) s_e[i] = g_tok_e[i];
    __syncthreads();
    int t = blockIdx.x * 256 + tid;
    int e = s_e[t];
    int r = 0;
#pragma unroll 4
    for (int u = 0; u < T_TOK; u++) {
        int eu = s_e[u];
        r += (eu < e) || (eu == e && u < t);
    }
    g_row[t] = r;
    g_order[r] = t;
    if (blockIdx.x == 0 && tid <= NE) {
        int c = 0;
#pragma unroll 4
        for (int u = 0; u < T_TOK; u++) c += (s_e[u] < tid);
        g_offs[tid] = c;
    }
}

// ---------------- scatter+convert hidden ----------------
__global__ void scatter_convert(const float* __restrict__ x) {
    int t = blockIdx.x, tid = threadIdx.x;
    int r = g_row[t];
    float s = g_tok_s[t];
    float4 v = ((const float4*)(x + (size_t)t * D_DIM))[tid];
    unsigned h0, l0, h1, l1;
    splith2(v.x, v.y, h0, l0); splith2(v.z, v.w, h1, l1);
    size_t o = ((size_t)t * D_DIM) / 2 + tid * 2;
    ((unsigned*)g_Xh)[o] = h0; ((unsigned*)g_Xh)[o + 1] = h1;
    ((unsigned*)g_Xl)[o] = l0; ((unsigned*)g_Xl)[o + 1] = l1;
    splith2(v.x * s, v.y * s, h0, l0); splith2(v.z * s, v.w * s, h1, l1);
    size_t o2 = ((size_t)r * D_DIM) / 2 + tid * 2;
    ((unsigned*)g_Xeh)[o2] = h0; ((unsigned*)g_Xeh)[o2 + 1] = h1;
    ((unsigned*)g_Xel)[o2] = l0; ((unsigned*)g_Xel)[o2 + 1] = l1;
}

// ================= gate+up GEMM: BK=32, 2-stage, A fp16 hi/lo, B single fp16 plane =================
// per-stage (bytes): Ah@0 (10240), Al@10240, G@20480 (4608), U@25088 -> 29696/stage
#define GU_STG 29696
#define GU_SMEM_BYTES (2 * GU_STG)
#define GU_LDA 40
#define GU_LDB 72

__global__ void __launch_bounds__(256, 2)
gemm_gateup_all(const float* __restrict__ w_gate, const float* __restrict__ w_up) {
    const int BK = 32;
    const int K = D_DIM, N = F_DIM;
    extern __shared__ __align__(16) char dsm[];

    int z = blockIdx.z;
    bool routed = (z > 0);
    int e = z - 1;
    int seg_start = 0, seg_rows = T_TOK;
    const __half *Ah, *Al;
    __half *Hh, *Hl;
    const float *Gf = nullptr, *Uf = nullptr;
    const __half *Gp = nullptr, *Upp = nullptr;
    if (routed) {
        seg_start = g_offs[e]; seg_rows = g_offs[e + 1] - seg_start;
        Ah = g_Xeh; Al = g_Xel;
        Gf = w_gate + (size_t)e * D_DIM * F_DIM;
        Uf = w_up   + (size_t)e * D_DIM * F_DIM;
        Hh = g_H2h; Hl = g_H2l;
    } else {
        Ah = g_Xh; Al = g_Xl;
        Gp = g_sWg16; Upp = g_sWu16;
        Hh = g_Hh; Hl = g_Hl;
    }
    int row0 = blockIdx.y * 128;
    if (row0 >= seg_rows) return;
    int col0 = blockIdx.x * 64;

    int tid = threadIdx.x, lane = tid & 31, wid = tid >> 5;
    int wm = wid & 3, wn = wid >> 2;

    auto pAh = [&](int buf) { return (__half*)(dsm + buf * GU_STG); };
    auto pAl = [&](int buf) { return (__half*)(dsm + buf * GU_STG + 10240); };
    auto pG  = [&](int buf) { return (__half*)(dsm + buf * GU_STG + 20480); };
    auto pU  = [&](int buf) { return (__half*)(dsm + buf * GU_STG + 25088); };

    // A staging: 128 rows x 4 chunks(8 halfs) per plane = 512 slots -> 2/thread/plane
    int ar[2], ac[2]; const __half *aph[2], *apl[2];
#pragma unroll
    for (int i = 0; i < 2; i++) {
        int idx = i * 256 + tid;
        ar[i] = idx >> 2; ac[i] = (idx & 3) * 8;
        int rg = row0 + ar[i]; if (rg >= seg_rows) rg = 0;   // clamp; discarded in epilogue
        aph[i] = Ah + (size_t)(seg_start + rg) * K + ac[i];
        apl[i] = Al + (size_t)(seg_start + rg) * K + ac[i];
    }
    // B shared path: 2 matrices x 256 slots (32 rows x 8 chunks); half-block per matrix, 2 slots each
    int bplq = tid >> 7, bsub = tid & 127;
    int br[2], bc[2]; const __half* bps[2] = { nullptr, nullptr };
#pragma unroll
    for (int i = 0; i < 2; i++) {
        int idx = i * 128 + bsub;
        br[i] = idx >> 3; bc[i] = (idx & 7) * 8;
        if (!routed) bps[i] = (bplq ? Upp : Gp) + (size_t)br[i] * N + col0 + bc[i];
    }
    // B routed path: 512 float4 per matrix -> 2/thread/matrix
    int bkr[2], bcc[2]; const float *gp[2] = { nullptr, nullptr }, *up[2] = { nullptr, nullptr };
#pragma unroll
    for (int i = 0; i < 2; i++) {
        int idx = i * 256 + tid;
        bkr[i] = idx >> 4; bcc[i] = (idx & 15) * 4;
        if (routed) {
            gp[i] = Gf + (size_t)bkr[i] * N + col0 + bcc[i];
            up[i] = Uf + (size_t)bkr[i] * N + col0 + bcc[i];
        }
    }

    float accg[2][4][4] = {}, accu[2][4][4] = {};

    auto stage_async = [&](int buf, int tile) {
        __half* sAh = pAh(buf); __half* sAl = pAl(buf);
#pragma unroll
        for (int i = 0; i < 2; i++) {
            cpa16(sAh + ar[i] * GU_LDA + ac[i], aph[i] + tile * BK);
            cpa16(sAl + ar[i] * GU_LDA + ac[i], apl[i] + tile * BK);
        }
        if (!routed) {
            __half* sB = bplq ? pU(buf) : pG(buf);
#pragma unroll
            for (int i = 0; i < 2; i++)
                cpa16(sB + br[i] * GU_LDB + bc[i], bps[i] + (size_t)tile * BK * N);
        }
        cpa_commit();
    };
    auto store_routedB = [&](int buf, const float4 gv[2], const float4 uv[2]) {
        __half* sG = pG(buf); __half* sU = pU(buf);
#pragma unroll
        for (int i = 0; i < 2; i++) {
            int off = bkr[i] * GU_LDB + bcc[i];
            *(unsigned*)&sG[off]     = cvt2(gv[i].x, gv[i].y);
            *(unsigned*)&sG[off + 2] = cvt2(gv[i].z, gv[i].w);
            *(unsigned*)&sU[off]     = cvt2(uv[i].x, uv[i].y);
            *(unsigned*)&sU[off + 2] = cvt2(uv[i].z, uv[i].w);
        }
    };

    auto compute = [&](int buf) {
        const __half* sAh = pAh(buf); const __half* sAl = pAl(buf);
        const __half* sG = pG(buf);  const __half* sU = pU(buf);
#pragma unroll
        for (int kh = 0; kh < 2; kh++) {
            unsigned ah[2][4], al[2][4];
#pragma unroll
            for (int mt = 0; mt < 2; mt++) {
                int r = wm * 32 + mt * 16 + (lane & 15);
                int kk = kh * 16 + (lane >> 4) * 8;
                ldsm4(ah[mt], sAh + r * GU_LDA + kk);
                ldsm4(al[mt], sAl + r * GU_LDA + kk);
            }
#pragma unroll
            for (int h = 0; h < 2; h++) {
                int krow = kh * 16 + (lane & 15);
                int nof = wn * 32 + h * 16 + (lane >> 4) * 8;
                unsigned gg[4], uu[4];
                ldsm4t(gg, sG + krow * GU_LDB + nof);
                ldsm4t(uu, sU + krow * GU_LDB + nof);
#pragma unroll
                for (int mt = 0; mt < 2; mt++)
#pragma unroll
                    for (int nn = 0; nn < 2; nn++) {
                        float* cg = accg[mt][h * 2 + nn];
                        float* cu = accu[mt][h * 2 + nn];
                        mma_f16(cg, ah[mt], gg[2*nn], gg[2*nn+1]);
                        mma_f16(cg, al[mt], gg[2*nn], gg[2*nn+1]);
                        mma_f16(cu, ah[mt], uu[2*nn], uu[2*nn+1]);
                        mma_f16(cu, al[mt], uu[2*nn], uu[2*nn+1]);
                    }
            }
        }
    };

    const int nC = K / BK;   // 32
    stage_async(0, 0);
    if (routed) {
        float4 gv[2] = { *(const float4*)gp[0], *(const float4*)gp[1] };
        float4 uv[2] = { *(const float4*)up[0], *(const float4*)up[1] };
        store_routedB(0, gv, uv);
    }
    cpa_wait_all();
    __syncthreads();

    for (int t = 0; t < nC; t++) {
        int buf = t & 1;
        bool more = (t + 1) < nC;
        float4 gv[2], uv[2];
        if (more) {
            stage_async(buf ^ 1, t + 1);
            if (routed) {
#pragma unroll
                for (int i = 0; i < 2; i++) {
                    gv[i] = *(const float4*)(gp[i] + (size_t)(t + 1) * BK * N);
                    uv[i] = *(const float4*)(up[i] + (size_t)(t + 1) * BK * N);
                }
            }
        }
        compute(buf);
        if (more) {
            if (routed) store_routedB(buf ^ 1, gv, uv);
            cpa_wait_all();
        }
        __syncthreads();
    }

    __half* Hhs = Hh + (size_t)seg_start * N;
    __half* Hls = Hl + (size_t)seg_start * N;
#pragma unroll
    for (int mt = 0; mt < 2; mt++)
#pragma unroll
        for (int nn = 0; nn < 4; nn++) {
            int r0 = row0 + wm * 32 + mt * 16 + (lane >> 2);
            int c = col0 + wn * 32 + nn * 8 + (lane & 3) * 2;
            float* cg = accg[mt][nn]; float* cu = accu[mt][nn];
            if (r0 < seg_rows) {
                unsigned h, l;
                splith2(silu_f(cg[0]) * cu[0], silu_f(cg[1]) * cu[1], h, l);
                ((unsigned*)Hhs)[((size_t)r0 * N + c) >> 1] = h;
                ((unsigned*)Hls)[((size_t)r0 * N + c) >> 1] = l;
            }
            int r1 = r0 + 8;
            if (r1 < seg_rows) {
                unsigned h, l;
                splith2(silu_f(cg[2]) * cu[2], silu_f(cg[3]) * cu[3], h, l);
                ((unsigned*)Hhs)[((size_t)r1 * N + c) >> 1] = h;
                ((unsigned*)Hls)[((size_t)r1 * N + c) >> 1] = l;
            }
        }
}

// ================= down GEMM: BK=32, 2-stage =================
// per-stage: Ah@0 (10240), Al@10240, B@20480 (8704) -> 29184/stage
#define DN_STG 29184
#define DN_SMEM_BYTES (2 * DN_STG)
#define DN_LDA 40
#define DN_LDB 136

__global__ void __launch_bounds__(256, 2)
gemm_down_all(float* __restrict__ out, const float* __restrict__ w_down) {
    const int BK = 32;
    const int K = F_DIM, N = D_DIM;
    extern __shared__ __align__(16) char dsm[];

    int z = blockIdx.z;
    bool routed = (z > 0);
    int e = z - 1;
    int seg_start = 0, seg_rows = T_TOK;
    const __half *Ah, *Al, *Bp = nullptr;
    const float* Bf = nullptr;
    if (routed) {
        seg_start = g_offs[e]; seg_rows = g_offs[e + 1] - seg_start;
        Ah = g_H2h; Al = g_H2l;
        Bf = w_down + (size_t)e * F_DIM * D_DIM;
    } else {
        Ah = g_Hh; Al = g_Hl; Bp = g_sWd16;
    }
    int row0 = blockIdx.y * 128;
    if (row0 >= seg_rows) return;
    int col0 = blockIdx.x * 128;

    int tid = threadIdx.x, lane = tid & 31, wid = tid >> 5;
    int wm = wid & 3, wn = wid >> 2;

    auto pAh = [&](int buf) { return (__half*)(dsm + buf * DN_STG); };
    auto pAl = [&](int buf) { return (__half*)(dsm + buf * DN_STG + 10240); };
    auto pB  = [&](int buf) { return (__half*)(dsm + buf * DN_STG + 20480); };

    int ar[2], ac[2]; const __half *aph[2], *apl[2];
#pragma unroll
    for (int i = 0; i < 2; i++) {
        int idx = i * 256 + tid;
        ar[i] = idx >> 2; ac[i] = (idx & 3) * 8;
        int rg = row0 + ar[i]; if (rg >= seg_rows) rg = 0;
        aph[i] = Ah + (size_t)(seg_start + rg) * K + ac[i];
        apl[i] = Al + (size_t)(seg_start + rg) * K + ac[i];
    }
    // shared B: 32 rows x 16 chunks = 512 slots -> 2/thread
    int br[2], bc[2]; const __half* bps[2] = { nullptr, nullptr };
#pragma unroll
    for (int i = 0; i < 2; i++) {
        int idx = i * 256 + tid;
        br[i] = idx >> 4; bc[i] = (idx & 15) * 8;
        if (!routed) bps[i] = Bp + (size_t)br[i] * N + col0 + bc[i];
    }
    // routed B fp32: 1024 float4 -> 4/thread
    int bkr[4], bcc[4]; const float* bp[4] = { nullptr, nullptr, nullptr, nullptr };
#pragma unroll
    for (int i = 0; i < 4; i++) {
        int idx = i * 256 + tid;
        bkr[i] = idx >> 5; bcc[i] = (idx & 31) * 4;
        if (routed) bp[i] = Bf + (size_t)bkr[i] * N + col0 + bcc[i];
    }

    float acc[2][8][4] = {};

    auto stage_async = [&](int buf, int tile) {
        __half* sAh = pAh(buf); __half* sAl = pAl(buf);
#pragma unroll
        for (int i = 0; i < 2; i++) {
            cpa16(sAh + ar[i] * DN_LDA + ac[i], aph[i] + tile * BK);
            cpa16(sAl + ar[i] * DN_LDA + ac[i], apl[i] + tile * BK);
        }
        if (!routed) {
            __half* sB = pB(buf);
#pragma unroll
            for (int i = 0; i < 2; i++)
                cpa16(sB + br[i] * DN_LDB + bc[i], bps[i] + (size_t)tile * BK * N);
        }
        cpa_commit();
    };
    auto store_routedB = [&](int buf, const float4 bv[4]) {
        __half* sB = pB(buf);
#pragma unroll
        for (int i = 0; i < 4; i++) {
            int off = bkr[i] * DN_LDB + bcc[i];
            *(unsigned*)&sB[off]     = cvt2(bv[i].x, bv[i].y);
            *(unsigned*)&sB[off + 2] = cvt2(bv[i].z, bv[i].w);
        }
    };

    auto compute = [&](int buf) {
        const __half* sAh = pAh(buf); const __half* sAl = pAl(buf);
        const __half* sB = pB(buf);
#pragma unroll
        for (int kh = 0; kh < 2; kh++) {
            unsigned ah[2][4], al[2][4];
#pragma unroll
            for (int mt = 0; mt < 2; mt++) {
                int r = wm * 32 + mt * 16 + (lane & 15);
                int kk = kh * 16 + (lane >> 4) * 8;
                ldsm4(ah[mt], sAh + r * DN_LDA + kk);
                ldsm4(al[mt], sAl + r * DN_LDA + kk);
            }
#pragma unroll
            for (int h = 0; h < 4; h++) {
                int krow = kh * 16 + (lane & 15);
                int nof = wn * 64 + h * 16 + (lane >> 4) * 8;
                unsigned bb[4];
                ldsm4t(bb, sB + krow * DN_LDB + nof);
#pragma unroll
                for (int mt = 0; mt < 2; mt++)
#pragma unroll
                    for (int nn = 0; nn < 2; nn++) {
                        float* c = acc[mt][h * 2 + nn];
                        mma_f16(c, ah[mt], bb[2*nn], bb[2*nn+1]);
                        mma_f16(c, al[mt], bb[2*nn], bb[2*nn+1]);
                    }
            }
        }
    };

    const int nC = K / BK;   // 64
    stage_async(0, 0);
    if (routed) {
        float4 bv0[4] = { *(const float4*)bp[0], *(const float4*)bp[1],
                          *(const float4*)bp[2], *(const float4*)bp[3] };
        store_routedB(0, bv0);
    }
    cpa_wait_all();
    __syncthreads();

    for (int t = 0; t < nC; t++) {
        int buf = t & 1;
        bool more = (t + 1) < nC;
        float4 bv[4];
        if (more) {
            stage_async(buf ^ 1, t + 1);
            if (routed) {
#pragma unroll
                for (int i = 0; i < 4; i++)
                    bv[i] = *(const float4*)(bp[i] + (size_t)(t + 1) * BK * N);
            }
        }
        compute(buf);
        if (more) {
            if (routed) store_routedB(buf ^ 1, bv);
            cpa_wait_all();
        }
        __syncthreads();
    }

#pragma unroll
    for (int mt = 0; mt < 2; mt++) {
        int rb0 = row0 + wm * 32 + mt * 16 + (lane >> 2);
        int rb1 = rb0 + 8;
        int tok0 = -1, tok1 = -1;
        if (rb0 < seg_rows) tok0 = routed ? g_order[seg_start + rb0] : rb0;
        if (rb1 < seg_rows) tok1 = routed ? g_order[seg_start + rb1] : rb1;
        float* dst = routed ? g_O2 : out;
#pragma unroll
        for (int nn = 0; nn < 8; nn++) {
            int c = col0 + wn * 64 + nn * 8 + (lane & 3) * 2;
            float* cc = acc[mt][nn];
            if (tok0 >= 0) { float2 v = { cc[0], cc[1] }; *(float2*)&dst[(size_t)tok0 * N + c] = v; }
            if (tok1 >= 0) { float2 v = { cc[2], cc[3] }; *(float2*)&dst[(size_t)tok1 * N + c] = v; }
        }
    }
}

// ---------------- final add ----------------
__global__ void add_kernel(float* __restrict__ out) {
    size_t i = (size_t)blockIdx.x * 256 + threadIdx.x;
    float4 v = ((float4*)out)[i];
    float4 w = ((const float4*)g_O2)[i];
    v.x += w.x; v.y += w.y; v.z += w.z; v.w += w.w;
    ((float4*)out)[i] = v;
}

extern "C" void kernel_launch(void* const* d_in, const int* in_sizes, int n_in,
                              void* d_out, int out_size) {
    const float* hidden   = (const float*)d_in[0];
    const float* router_w = (const float*)d_in[1];
    const float* w_gate   = (const float*)d_in[2];
    const float* w_up     = (const float*)d_in[3];
    const float* w_down   = (const float*)d_in[4];
    const float* ws_gate  = (const float*)d_in[5];
    const float* ws_up    = (const float*)d_in[6];
    const float* ws_down  = (const float*)d_in[7];
    float* out = (float*)d_out;

    cudaFuncSetAttribute(gemm_gateup_all, cudaFuncAttributeMaxDynamicSharedMemorySize, GU_SMEM_BYTES);
    cudaFuncSetAttribute(gemm_down_all,   cudaFuncAttributeMaxDynamicSharedMemorySize, DN_SMEM_BYTES);

    conv_shared<<<512, 256>>>(ws_gate, ws_up, ws_down);
    router_kernel<<<T_TOK, 256>>>(hidden, router_w);
    rank_kernel<<<T_TOK / 256, 256>>>();
    scatter_convert<<<T_TOK, 256>>>(hidden);

    dim3 gridGU(F_DIM / 64, T_TOK / 128, NE + 1);
    gemm_gateup_all<<<gridGU, 256, GU_SMEM_BYTES>>>(w_gate, w_up);
    dim3 gridDN(D_DIM / 128, T_TOK / 128, NE + 1);
    gemm_down_all<<<gridDN, 256, DN_SMEM_BYTES>>>(out, w_down);
    add_kernel<<<(T_TOK * D_DIM / 4) / 256, 256>>>(out);

    (void)in_sizes; (void)n_in; (void)out_size;
}

// round 15
// speedup vs baseline: 2.0061x; 1.3355x over previous
#include <cuda_runtime.h>
#include <cuda_fp16.h>
#include <cstdint>
#include <math.h>

#define T_TOK 2048
#define D_DIM 1024
#define F_DIM 2048
#define NE 8

// ---- scratch: referenced ONLY inside device code ----
__device__ __half g_sWg16[(size_t)D_DIM * F_DIM];
__device__ __half g_sWu16[(size_t)D_DIM * F_DIM];
__device__ __half g_sWd16[(size_t)F_DIM * D_DIM];
__device__ __half g_X16 [(size_t)T_TOK * D_DIM];   // hidden fp16 (token order)
__device__ __half g_Xe16[(size_t)T_TOK * D_DIM];   // scaled fp16 (grouped order)
__device__ __half g_H16 [(size_t)T_TOK * F_DIM];   // shared H fp16
__device__ __half g_H216[(size_t)T_TOK * F_DIM];   // routed H fp16
__device__ float g_O2[(size_t)T_TOK * D_DIM];
__device__ int   g_tok_e[T_TOK];
__device__ float g_tok_s[T_TOK];
__device__ int   g_row[T_TOK];
__device__ int   g_order[T_TOK];
__device__ int   g_offs[NE + 1];

__device__ __forceinline__ float silu_f(float x) { return x / (1.0f + expf(-x)); }

__device__ __forceinline__ unsigned cvt2(float x0, float x1) {
    return (unsigned)__half_as_ushort(__float2half_rn(x0))
         | ((unsigned)__half_as_ushort(__float2half_rn(x1)) << 16);
}

__device__ __forceinline__ void cpa16(void* smem, const void* gmem) {
    unsigned s = (unsigned)__cvta_generic_to_shared(smem);
    asm volatile("cp.async.cg.shared.global [%0], [%1], 16;" :: "r"(s), "l"(gmem));
}
__device__ __forceinline__ void cpa_commit() { asm volatile("cp.async.commit_group;"); }
__device__ __forceinline__ void cpa_wait_all() { asm volatile("cp.async.wait_group 0;" ::: "memory"); }

__device__ __forceinline__ void ldsm4(unsigned r[4], const void* p) {
    unsigned a = (unsigned)__cvta_generic_to_shared(p);
    asm volatile("ldmatrix.sync.aligned.m8n8.x4.shared.b16 {%0,%1,%2,%3}, [%4];"
                 : "=r"(r[0]), "=r"(r[1]), "=r"(r[2]), "=r"(r[3]) : "r"(a));
}
__device__ __forceinline__ void ldsm4t(unsigned r[4], const void* p) {
    unsigned a = (unsigned)__cvta_generic_to_shared(p);
    asm volatile("ldmatrix.sync.aligned.m8n8.x4.trans.shared.b16 {%0,%1,%2,%3}, [%4];"
                 : "=r"(r[0]), "=r"(r[1]), "=r"(r[2]), "=r"(r[3]) : "r"(a));
}
__device__ __forceinline__ void mma_f16(float c[4], const unsigned a[4], unsigned b0, unsigned b1) {
    asm volatile(
        "mma.sync.aligned.m16n8k16.row.col.f32.f16.f16.f32 "
        "{%0,%1,%2,%3}, {%4,%5,%6,%7}, {%8,%9}, {%0,%1,%2,%3};"
        : "+f"(c[0]), "+f"(c[1]), "+f"(c[2]), "+f"(c[3])
        : "r"(a[0]), "r"(a[1]), "r"(a[2]), "r"(a[3]), "r"(b0), "r"(b1));
}

// ---------------- convert shared weights ----------------
__global__ void conv_shared(const float* __restrict__ g, const float* __restrict__ u,
                            const float* __restrict__ d) {
    const int n4 = D_DIM * F_DIM / 4;
    for (int idx = blockIdx.x * 256 + threadIdx.x; idx < 3 * n4; idx += gridDim.x * 256) {
        int which = idx / n4, i = idx - which * n4;
        const float* src = (which == 0) ? g : (which == 1) ? u : d;
        __half* dst = (which == 0) ? g_sWg16 : (which == 1) ? g_sWu16 : g_sWd16;
        float4 v = ((const float4*)src)[i];
        ((unsigned*)dst)[2 * i]     = cvt2(v.x, v.y);
        ((unsigned*)dst)[2 * i + 1] = cvt2(v.z, v.w);
    }
}

// ---------------- router ----------------
__global__ void router_kernel(const float* __restrict__ x, const float* __restrict__ rw) {
    __shared__ float red[256][NE + 1];
    int t = blockIdx.x, tid = threadIdx.x;
    float4 xa = ((const float4*)(x + (size_t)t * D_DIM))[tid];
#pragma unroll
    for (int e = 0; e < NE; e++) {
        float4 wv = ((const float4*)(rw + (size_t)e * D_DIM))[tid];
        red[tid][e] = xa.x * wv.x + xa.y * wv.y + xa.z * wv.z + xa.w * wv.w;
    }
    __syncthreads();
    for (int s = 128; s > 0; s >>= 1) {
        if (tid < s)
#pragma unroll
            for (int e = 0; e < NE; e++) red[tid][e] += red[tid + s][e];
        __syncthreads();
    }
    if (tid == 0) {
        float bv = red[0][0]; int be = 0;
#pragma unroll
        for (int e = 1; e < NE; e++) if (red[0][e] > bv) { bv = red[0][e]; be = e; }
        g_tok_e[t] = be;
        g_tok_s[t] = 1.0f / (1.0f + expf(-bv));
    }
}

// ---------------- stable rank + offsets ----------------
__global__ void rank_kernel() {
    __shared__ int s_e[T_TOK];
    int tid = threadIdx.x;
    for (int i = tid; i < T_TOK; i += 256) s_e[i] = g_tok_e[i];
    __syncthreads();
    int t = blockIdx.x * 256 + tid;
    int e = s_e[t];
    int r = 0;
#pragma unroll 4
    for (int u = 0; u < T_TOK; u++) {
        int eu = s_e[u];
        r += (eu < e) || (eu == e && u < t);
    }
    g_row[t] = r;
    g_order[r] = t;
    if (blockIdx.x == 0 && tid <= NE) {
        int c = 0;
#pragma unroll 4
        for (int u = 0; u < T_TOK; u++) c += (s_e[u] < tid);
        g_offs[tid] = c;
    }
}

// ---------------- scatter+convert hidden (single fp16 plane each) ----------------
__global__ void scatter_convert(const float* __restrict__ x) {
    int t = blockIdx.x, tid = threadIdx.x;
    int r = g_row[t];
    float s = g_tok_s[t];
    float4 v = ((const float4*)(x + (size_t)t * D_DIM))[tid];
    size_t o = ((size_t)t * D_DIM) / 2 + tid * 2;
    ((unsigned*)g_X16)[o]     = cvt2(v.x, v.y);
    ((unsigned*)g_X16)[o + 1] = cvt2(v.z, v.w);
    size_t o2 = ((size_t)r * D_DIM) / 2 + tid * 2;
    ((unsigned*)g_Xe16)[o2]     = cvt2(v.x * s, v.y * s);
    ((unsigned*)g_Xe16)[o2 + 1] = cvt2(v.z * s, v.w * s);
}

// ================= gate+up GEMM: BK=32, 2-stage, pure fp16 =================
// per-stage (bytes): A@0 (10240), G@10240 (4608), U@14848 -> 19456/stage
#define GU_STG 19456
#define GU_SMEM_BYTES (2 * GU_STG)
#define GU_LDA 40
#define GU_LDB 72

__global__ void __launch_bounds__(256, 2)
gemm_gateup_all(const float* __restrict__ w_gate, const float* __restrict__ w_up) {
    const int BK = 32;
    const int K = D_DIM, N = F_DIM;
    extern __shared__ __align__(16) char dsm[];

    int z = blockIdx.z;
    bool routed = (z > 0);
    int e = z - 1;
    int seg_start = 0, seg_rows = T_TOK;
    const __half *A16;
    __half *H16;
    const float *Gf = nullptr, *Uf = nullptr;
    const __half *Gp = nullptr, *Upp = nullptr;
    if (routed) {
        seg_start = g_offs[e]; seg_rows = g_offs[e + 1] - seg_start;
        A16 = g_Xe16;
        Gf = w_gate + (size_t)e * D_DIM * F_DIM;
        Uf = w_up   + (size_t)e * D_DIM * F_DIM;
        H16 = g_H216;
    } else {
        A16 = g_X16;
        Gp = g_sWg16; Upp = g_sWu16;
        H16 = g_H16;
    }
    int row0 = blockIdx.y * 128;
    if (row0 >= seg_rows) return;
    int col0 = blockIdx.x * 64;

    int tid = threadIdx.x, lane = tid & 31, wid = tid >> 5;
    int wm = wid & 3, wn = wid >> 2;

    auto pA = [&](int buf) { return (__half*)(dsm + buf * GU_STG); };
    auto pG = [&](int buf) { return (__half*)(dsm + buf * GU_STG + 10240); };
    auto pU = [&](int buf) { return (__half*)(dsm + buf * GU_STG + 14848); };

    // A staging: 128 rows x 4 chunks = 512 slots -> 2/thread
    int ar[2], ac[2]; const __half* ap[2];
#pragma unroll
    for (int i = 0; i < 2; i++) {
        int idx = i * 256 + tid;
        ar[i] = idx >> 2; ac[i] = (idx & 3) * 8;
        int rg = row0 + ar[i]; if (rg >= seg_rows) rg = 0;   // clamp; discarded in epilogue
        ap[i] = A16 + (size_t)(seg_start + rg) * K + ac[i];
    }
    // B shared path: 2 matrices x 256 slots (32 rows x 8 chunks); half-block per matrix, 2 slots each
    int bplq = tid >> 7, bsub = tid & 127;
    int br[2], bc[2]; const __half* bps[2] = { nullptr, nullptr };
#pragma unroll
    for (int i = 0; i < 2; i++) {
        int idx = i * 128 + bsub;
        br[i] = idx >> 3; bc[i] = (idx & 7) * 8;
        if (!routed) bps[i] = (bplq ? Upp : Gp) + (size_t)br[i] * N + col0 + bc[i];
    }
    // B routed path: 512 float4 per matrix -> 2/thread/matrix
    int bkr[2], bcc[2]; const float *gp[2] = { nullptr, nullptr }, *up[2] = { nullptr, nullptr };
#pragma unroll
    for (int i = 0; i < 2; i++) {
        int idx = i * 256 + tid;
        bkr[i] = idx >> 4; bcc[i] = (idx & 15) * 4;
        if (routed) {
            gp[i] = Gf + (size_t)bkr[i] * N + col0 + bcc[i];
            up[i] = Uf + (size_t)bkr[i] * N + col0 + bcc[i];
        }
    }

    float accg[2][4][4] = {}, accu[2][4][4] = {};

    auto stage_async = [&](int buf, int tile) {
        __half* sA = pA(buf);
#pragma unroll
        for (int i = 0; i < 2; i++)
            cpa16(sA + ar[i] * GU_LDA + ac[i], ap[i] + tile * BK);
        if (!routed) {
            __half* sB = bplq ? pU(buf) : pG(buf);
#pragma unroll
            for (int i = 0; i < 2; i++)
                cpa16(sB + br[i] * GU_LDB + bc[i], bps[i] + (size_t)tile * BK * N);
        }
        cpa_commit();
    };
    auto store_routedB = [&](int buf, const float4 gv[2], const float4 uv[2]) {
        __half* sG = pG(buf); __half* sU = pU(buf);
#pragma unroll
        for (int i = 0; i < 2; i++) {
            int off = bkr[i] * GU_LDB + bcc[i];
            *(unsigned*)&sG[off]     = cvt2(gv[i].x, gv[i].y);
            *(unsigned*)&sG[off + 2] = cvt2(gv[i].z, gv[i].w);
            *(unsigned*)&sU[off]     = cvt2(uv[i].x, uv[i].y);
            *(unsigned*)&sU[off + 2] = cvt2(uv[i].z, uv[i].w);
        }
    };

    auto compute = [&](int buf) {
        const __half* sA = pA(buf);
        const __half* sG = pG(buf);
        const __half* sU = pU(buf);
#pragma unroll
        for (int kh = 0; kh < 2; kh++) {
            unsigned a[2][4];
#pragma unroll
            for (int mt = 0; mt < 2; mt++) {
                int r = wm * 32 + mt * 16 + (lane & 15);
                int kk = kh * 16 + (lane >> 4) * 8;
                ldsm4(a[mt], sA + r * GU_LDA + kk);
            }
#pragma unroll
            for (int h = 0; h < 2; h++) {
                int krow = kh * 16 + (lane & 15);
                int nof = wn * 32 + h * 16 + (lane >> 4) * 8;
                unsigned gg[4], uu[4];
                ldsm4t(gg, sG + krow * GU_LDB + nof);
                ldsm4t(uu, sU + krow * GU_LDB + nof);
#pragma unroll
                for (int mt = 0; mt < 2; mt++)
#pragma unroll
                    for (int nn = 0; nn < 2; nn++) {
                        mma_f16(accg[mt][h * 2 + nn], a[mt], gg[2*nn], gg[2*nn+1]);
                        mma_f16(accu[mt][h * 2 + nn], a[mt], uu[2*nn], uu[2*nn+1]);
                    }
            }
        }
    };

    const int nC = K / BK;   // 32
    stage_async(0, 0);
    if (routed) {
        float4 gv[2] = { *(const float4*)gp[0], *(const float4*)gp[1] };
        float4 uv[2] = { *(const float4*)up[0], *(const float4*)up[1] };
        store_routedB(0, gv, uv);
    }
    cpa_wait_all();
    __syncthreads();

    for (int t = 0; t < nC; t++) {
        int buf = t & 1;
        bool more = (t + 1) < nC;
        float4 gv[2], uv[2];
        if (more) {
            stage_async(buf ^ 1, t + 1);
            if (routed) {
#pragma unroll
                for (int i = 0; i < 2; i++) {
                    gv[i] = *(const float4*)(gp[i] + (size_t)(t + 1) * BK * N);
                    uv[i] = *(const float4*)(up[i] + (size_t)(t + 1) * BK * N);
                }
            }
        }
        compute(buf);
        if (more) {
            if (routed) store_routedB(buf ^ 1, gv, uv);
            cpa_wait_all();
        }
        __syncthreads();
    }

    __half* Hs = H16 + (size_t)seg_start * N;
#pragma unroll
    for (int mt = 0; mt < 2; mt++)
#pragma unroll
        for (int nn = 0; nn < 4; nn++) {
            int r0 = row0 + wm * 32 + mt * 16 + (lane >> 2);
            int c = col0 + wn * 32 + nn * 8 + (lane & 3) * 2;
            float* cg = accg[mt][nn]; float* cu = accu[mt][nn];
            if (r0 < seg_rows)
                ((unsigned*)Hs)[((size_t)r0 * N + c) >> 1] =
                    cvt2(silu_f(cg[0]) * cu[0], silu_f(cg[1]) * cu[1]);
            int r1 = r0 + 8;
            if (r1 < seg_rows)
                ((unsigned*)Hs)[((size_t)r1 * N + c) >> 1] =
                    cvt2(silu_f(cg[2]) * cu[2], silu_f(cg[3]) * cu[3]);
        }
}

// ================= down GEMM: BK=32, 2-stage, pure fp16 =================
// per-stage: A@0 (10240), B@10240 (8704) -> 18944/stage
#define DN_STG 18944
#define DN_SMEM_BYTES (2 * DN_STG)
#define DN_LDA 40
#define DN_LDB 136

__global__ void __launch_bounds__(256, 2)
gemm_down_all(float* __restrict__ out, const float* __restrict__ w_down) {
    const int BK = 32;
    const int K = F_DIM, N = D_DIM;
    extern __shared__ __align__(16) char dsm[];

    int z = blockIdx.z;
    bool routed = (z > 0);
    int e = z - 1;
    int seg_start = 0, seg_rows = T_TOK;
    const __half *A16, *Bp = nullptr;
    const float* Bf = nullptr;
    if (routed) {
        seg_start = g_offs[e]; seg_rows = g_offs[e + 1] - seg_start;
        A16 = g_H216;
        Bf = w_down + (size_t)e * F_DIM * D_DIM;
    } else {
        A16 = g_H16; Bp = g_sWd16;
    }
    int row0 = blockIdx.y * 128;
    if (row0 >= seg_rows) return;
    int col0 = blockIdx.x * 128;

    int tid = threadIdx.x, lane = tid & 31, wid = tid >> 5;
    int wm = wid & 3, wn = wid >> 2;

    auto pA = [&](int buf) { return (__half*)(dsm + buf * DN_STG); };
    auto pB = [&](int buf) { return (__half*)(dsm + buf * DN_STG + 10240); };

    int ar[2], ac[2]; const __half* ap[2];
#pragma unroll
    for (int i = 0; i < 2; i++) {
        int idx = i * 256 + tid;
        ar[i] = idx >> 2; ac[i] = (idx & 3) * 8;
        int rg = row0 + ar[i]; if (rg >= seg_rows) rg = 0;
        ap[i] = A16 + (size_t)(seg_start + rg) * K + ac[i];
    }
    // shared B: 32 rows x 16 chunks = 512 slots -> 2/thread
    int br[2], bc[2]; const __half* bps[2] = { nullptr, nullptr };
#pragma unroll
    for (int i = 0; i < 2; i++) {
        int idx = i * 256 + tid;
        br[i] = idx >> 4; bc[i] = (idx & 15) * 8;
        if (!routed) bps[i] = Bp + (size_t)br[i] * N + col0 + bc[i];
    }
    // routed B fp32: 1024 float4 -> 4/thread
    int bkr[4], bcc[4]; const float* bp[4] = { nullptr, nullptr, nullptr, nullptr };
#pragma unroll
    for (int i = 0; i < 4; i++) {
        int idx = i * 256 + tid;
        bkr[i] = idx >> 5; bcc[i] = (idx & 31) * 4;
        if (routed) bp[i] = Bf + (size_t)bkr[i] * N + col0 + bcc[i];
    }

    float acc[2][8][4] = {};

    auto stage_async = [&](int buf, int tile) {
        __half* sA = pA(buf);
#pragma unroll
        for (int i = 0; i < 2; i++)
            cpa16(sA + ar[i] * DN_LDA + ac[i], ap[i] + tile * BK);
        if (!routed) {
            __half* sB = pB(buf);
#pragma unroll
            for (int i = 0; i < 2; i++)
                cpa16(sB + br[i] * DN_LDB + bc[i], bps[i] + (size_t)tile * BK * N);
        }
        cpa_commit();
    };
    auto store_routedB = [&](int buf, const float4 bv[4]) {
        __half* sB = pB(buf);
#pragma unroll
        for (int i = 0; i < 4; i++) {
            int off = bkr[i] * DN_LDB + bcc[i];
            *(unsigned*)&sB[off]     = cvt2(bv[i].x, bv[i].y);
            *(unsigned*)&sB[off + 2] = cvt2(bv[i].z, bv[i].w);
        }
    };

    auto compute = [&](int buf) {
        const __half* sA = pA(buf);
        const __half* sB = pB(buf);
#pragma unroll
        for (int kh = 0; kh < 2; kh++) {
            unsigned a[2][4];
#pragma unroll
            for (int mt = 0; mt < 2; mt++) {
                int r = wm * 32 + mt * 16 + (lane & 15);
                int kk = kh * 16 + (lane >> 4) * 8;
                ldsm4(a[mt], sA + r * DN_LDA + kk);
            }
#pragma unroll
            for (int h = 0; h < 4; h++) {
                int krow = kh * 16 + (lane & 15);
                int nof = wn * 64 + h * 16 + (lane >> 4) * 8;
                unsigned bb[4];
                ldsm4t(bb, sB + krow * DN_LDB + nof);
#pragma unroll
                for (int mt = 0; mt < 2; mt++)
#pragma unroll
                    for (int nn = 0; nn < 2; nn++)
                        mma_f16(acc[mt][h * 2 + nn], a[mt], bb[2*nn], bb[2*nn+1]);
            }
        }
    };

    const int nC = K / BK;   // 64
    stage_async(0, 0);
    if (routed) {
        float4 bv0[4] = { *(const float4*)bp[0], *(const float4*)bp[1],
                          *(const float4*)bp[2], *(const float4*)bp[3] };
        store_routedB(0, bv0);
    }
    cpa_wait_all();
    __syncthreads();

    for (int t = 0; t < nC; t++) {
        int buf = t & 1;
        bool more = (t + 1) < nC;
        float4 bv[4];
        if (more) {
            stage_async(buf ^ 1, t + 1);
            if (routed) {
#pragma unroll
                for (int i = 0; i < 4; i++)
                    bv[i] = *(const float4*)(bp[i] + (size_t)(t + 1) * BK * N);
            }
        }
        compute(buf);
        if (more) {
            if (routed) store_routedB(buf ^ 1, bv);
            cpa_wait_all();
        }
        __syncthreads();
    }

#pragma unroll
    for (int mt = 0; mt < 2; mt++) {
        int rb0 = row0 + wm * 32 + mt * 16 + (lane >> 2);
        int rb1 = rb0 + 8;
        int tok0 = -1, tok1 = -1;
        if (rb0 < seg_rows) tok0 = routed ? g_order[seg_start + rb0] : rb0;
        if (rb1 < seg_rows) tok1 = routed ? g_order[seg_start + rb1] : rb1;
        float* dst = routed ? g_O2 : out;
#pragma unroll
        for (int nn = 0; nn < 8; nn++) {
            int c = col0 + wn * 64 + nn * 8 + (lane & 3) * 2;
            float* cc = acc[mt][nn];
            if (tok0 >= 0) { float2 v = { cc[0], cc[1] }; *(float2*)&dst[(size_t)tok0 * N + c] = v; }
            if (tok1 >= 0) { float2 v = { cc[2], cc[3] }; *(float2*)&dst[(size_t)tok1 * N + c] = v; }
        }
    }
}

// ---------------- final add ----------------
__global__ void add_kernel(float* __restrict__ out) {
    size_t i = (size_t)blockIdx.x * 256 + threadIdx.x;
    float4 v = ((float4*)out)[i];
    float4 w = ((const float4*)g_O2)[i];
    v.x += w.x; v.y += w.y; v.z += w.z; v.w += w.w;
    ((float4*)out)[i] = v;
}

extern "C" void kernel_launch(void* const* d_in, const int* in_sizes, int n_in,
                              void* d_out, int out_size) {
    const float* hidden   = (const float*)d_in[0];
    const float* router_w = (const float*)d_in[1];
    const float* w_gate   = (const float*)d_in[2];
    const float* w_up     = (const float*)d_in[3];
    const float* w_down   = (const float*)d_in[4];
    const float* ws_gate  = (const float*)d_in[5];
    const float* ws_up    = (const float*)d_in[6];
    const float* ws_down  = (const float*)d_in[7];
    float* out = (float*)d_out;

    cudaFuncSetAttribute(gemm_gateup_all, cudaFuncAttributeMaxDynamicSharedMemorySize, GU_SMEM_BYTES);
    cudaFuncSetAttribute(gemm_down_all,   cudaFuncAttributeMaxDynamicSharedMemorySize, DN_SMEM_BYTES);

    conv_shared<<<512, 256>>>(ws_gate, ws_up, ws_down);
    router_kernel<<<T_TOK, 256>>>(hidden, router_w);
    rank_kernel<<<T_TOK / 256, 256>>>();
    scatter_convert<<<T_TOK, 256>>>(hidden);

    dim3 gridGU(F_DIM / 64, T_TOK / 128, NE + 1);
    gemm_gateup_all<<<gridGU, 256, GU_SMEM_BYTES>>>(w_gate, w_up);
    dim3 gridDN(D_DIM / 128, T_TOK / 128, NE + 1);
    gemm_down_all<<<gridDN, 256, DN_SMEM_BYTES>>>(out, w_down);
    add_kernel<<<(T_TOK * D_DIM / 4) / 256, 256>>>(out);

    (void)in_sizes; (void)n_in; (void)out_size;
}